// round 1
// baseline (speedup 1.0000x reference)
#include <cuda_runtime.h>
#include <cuda_bf16.h>

#define N_NODES 20000
#define E_EDGES 640000
#define IN_DIM  24
#define H       128
#define OUT_DIM 24
#define MAPD    512

// ---------------- scratch (device globals; no allocation) ----------------
__device__ float g_hemb[N_NODES * H];
__device__ float g_hA[N_NODES * H];
__device__ float g_hB[N_NODES * H];
__device__ float g_hs[N_NODES * H];
__device__ float g_z[N_NODES * H];
__device__ float g_ssrc[N_NODES];
__device__ float g_sdst[N_NODES];
__device__ int   g_offs[N_NODES + 1];
__device__ int   g_cnt[N_NODES];
__device__ int   g_cur[N_NODES];
__device__ int   g_csrc[E_EDGES];

// ---------------- CSR build ----------------
__global__ void k_zero_counters() {
    int i = blockIdx.x * blockDim.x + threadIdx.x;
    if (i < N_NODES) { g_cnt[i] = 0; g_cur[i] = 0; }
}

__global__ void k_hist(const int* __restrict__ dst) {
    int e = blockIdx.x * blockDim.x + threadIdx.x;
    if (e < E_EDGES) atomicAdd(&g_cnt[dst[e]], 1);
}

__global__ void k_scan() {
    __shared__ int sdata[1024];
    __shared__ int s_carry;
    int tid = threadIdx.x;
    if (tid == 0) s_carry = 0;
    __syncthreads();
    for (int base = 0; base < N_NODES; base += 1024) {
        int i = base + tid;
        int v = (i < N_NODES) ? g_cnt[i] : 0;
        sdata[tid] = v;
        __syncthreads();
        // inclusive Hillis-Steele scan
        #pragma unroll
        for (int off = 1; off < 1024; off <<= 1) {
            int t = (tid >= off) ? sdata[tid - off] : 0;
            __syncthreads();
            sdata[tid] += t;
            __syncthreads();
        }
        int incl = sdata[tid];
        int carry = s_carry;
        if (i < N_NODES) g_offs[i] = carry + incl - v;  // exclusive
        __syncthreads();
        if (tid == 1023) s_carry = carry + incl;
        __syncthreads();
    }
    if (tid == 0) g_offs[N_NODES] = s_carry;
}

__global__ void k_scatter(const int* __restrict__ src, const int* __restrict__ dst) {
    int e = blockIdx.x * blockDim.x + threadIdx.x;
    if (e < E_EDGES) {
        int d = dst[e];
        int p = g_offs[d] + atomicAdd(&g_cur[d], 1);
        g_csrc[p] = src[e];
    }
}

// ---------------- embedding: h_emb = feats @ W_eh^T + b_eh ----------------
__global__ void k_embed(const float* __restrict__ feats,
                        const float* __restrict__ W_eh,
                        const float* __restrict__ b_eh) {
    int n = blockIdx.x;
    __shared__ float f[IN_DIM];
    if (threadIdx.x < IN_DIM) f[threadIdx.x] = feats[n * IN_DIM + threadIdx.x];
    __syncthreads();
    int h = threadIdx.x;
    float acc = b_eh[h];
    #pragma unroll
    for (int k = 0; k < IN_DIM; k++) acc += f[k] * W_eh[h * IN_DIM + k];
    g_hemb[n * H + h] = acc;
}

// ---------------- tiled GEMM: C[N,128] = X[N,K] @ W[128,K]^T (+bias)(relu) ----------------
// CONCAT: X[n,k] = (k < MAPD) ? A0[n*MAPD+k] : A1[n*H + k-MAPD]
template <int KDIM, bool DO_RELU, bool HAS_BIAS, bool CONCAT>
__global__ void __launch_bounds__(256)
k_gemm(const float* __restrict__ A0, const float* __restrict__ A1,
       const float* __restrict__ W,  const float* __restrict__ bias,
       float* __restrict__ C) {
    const int BM = 64, BN = 128, BK = 16;
    __shared__ float As[BK][BM + 4];
    __shared__ float Bs[BK][BN + 4];
    int tid = threadIdx.x;            // 256 threads
    int row0 = blockIdx.x * BM;
    int tx = tid & 31;                // cols tx*4 .. +3
    int ty = tid >> 5;                // rows ty*8 .. +7

    float acc[8][4];
    #pragma unroll
    for (int i = 0; i < 8; i++)
        #pragma unroll
        for (int j = 0; j < 4; j++) acc[i][j] = 0.f;

    int kinA = tid & 15, rrA = tid >> 4;

    for (int k0 = 0; k0 < KDIM; k0 += BK) {
        // A tile 64x16
        #pragma unroll
        for (int p = 0; p < 4; p++) {
            int r = rrA + p * 16;
            int grow = row0 + r;
            int gk = k0 + kinA;
            float v = 0.f;
            if (grow < N_NODES) {
                if (CONCAT) v = (gk < MAPD) ? A0[grow * MAPD + gk]
                                            : A1[grow * H + (gk - MAPD)];
                else        v = A0[grow * KDIM + gk];
            }
            As[kinA][r] = v;
        }
        // B tile 16x128 (transposed W)
        #pragma unroll
        for (int p = 0; p < 8; p++) {
            int h = (tid >> 4) + p * 16;
            int gk = k0 + (tid & 15);
            Bs[tid & 15][h] = W[h * KDIM + gk];
        }
        __syncthreads();
        #pragma unroll
        for (int kk = 0; kk < BK; kk++) {
            float4 a0 = *(const float4*)&As[kk][ty * 8];
            float4 a1 = *(const float4*)&As[kk][ty * 8 + 4];
            float4 bv = *(const float4*)&Bs[kk][tx * 4];
            float av[8] = {a0.x, a0.y, a0.z, a0.w, a1.x, a1.y, a1.z, a1.w};
            float bw[4] = {bv.x, bv.y, bv.z, bv.w};
            #pragma unroll
            for (int i = 0; i < 8; i++)
                #pragma unroll
                for (int j = 0; j < 4; j++)
                    acc[i][j] += av[i] * bw[j];
        }
        __syncthreads();
    }

    float4 bv = make_float4(0.f, 0.f, 0.f, 0.f);
    if (HAS_BIAS) bv = *(const float4*)&bias[tx * 4];
    #pragma unroll
    for (int i = 0; i < 8; i++) {
        int row = row0 + ty * 8 + i;
        if (row < N_NODES) {
            float4 r;
            r.x = acc[i][0] + bv.x;
            r.y = acc[i][1] + bv.y;
            r.z = acc[i][2] + bv.z;
            r.w = acc[i][3] + bv.w;
            if (DO_RELU) {
                r.x = fmaxf(r.x, 0.f); r.y = fmaxf(r.y, 0.f);
                r.z = fmaxf(r.z, 0.f); r.w = fmaxf(r.w, 0.f);
            }
            *(float4*)&C[row * H + tx * 4] = r;
        }
    }
}

// ---------------- per-node attention halves: s_src = z@a[:H], s_dst = z@a[H:] ----------------
__global__ void k_sdot(const float* __restrict__ a) {
    int warp = (blockIdx.x * blockDim.x + threadIdx.x) >> 5;
    int lane = threadIdx.x & 31;
    if (warp >= N_NODES) return;
    float4 zv = *(const float4*)&g_z[warp * H + lane * 4];
    float4 a0 = *(const float4*)&a[lane * 4];
    float4 a1 = *(const float4*)&a[H + lane * 4];
    float s0 = zv.x * a0.x + zv.y * a0.y + zv.z * a0.z + zv.w * a0.w;
    float s1 = zv.x * a1.x + zv.y * a1.y + zv.z * a1.z + zv.w * a1.w;
    #pragma unroll
    for (int off = 16; off; off >>= 1) {
        s0 += __shfl_xor_sync(0xffffffffu, s0, off);
        s1 += __shfl_xor_sync(0xffffffffu, s1, off);
    }
    if (lane == 0) { g_ssrc[warp] = s0; g_sdst[warp] = s1; }
}

// ---------------- fused GAT edge kernel: warp per dst node ----------------
__global__ void k_gat(const float* __restrict__ hin, float* __restrict__ hout) {
    int node = blockIdx.x * (blockDim.x >> 5) + (threadIdx.x >> 5);
    int lane = threadIdx.x & 31;
    if (node >= N_NODES) return;
    int beg = g_offs[node], end = g_offs[node + 1];
    float4 hi = *(const float4*)&hin[node * H + lane * 4];
    if (beg == end) {  // zero in-degree: out = h_in + h_in
        float4 o = make_float4(2.f * hi.x, 2.f * hi.y, 2.f * hi.z, 2.f * hi.w);
        *(float4*)&hout[node * H + lane * 4] = o;
        return;
    }
    float sd = g_sdst[node];
    // pass 1: max
    float mx = -3.0e38f;
    for (int j = beg + lane; j < end; j += 32) {
        float x = g_ssrc[g_csrc[j]] + sd;
        mx = fmaxf(mx, fmaxf(x, 0.01f * x));   // leaky_relu(x, 0.01)
    }
    #pragma unroll
    for (int off = 16; off; off >>= 1) mx = fmaxf(mx, __shfl_xor_sync(0xffffffffu, mx, off));
    // pass 2: denom
    float den = 0.f;
    for (int j = beg + lane; j < end; j += 32) {
        float x = g_ssrc[g_csrc[j]] + sd;
        den += __expf(fmaxf(x, 0.01f * x) - mx);
    }
    #pragma unroll
    for (int off = 16; off; off >>= 1) den += __shfl_xor_sync(0xffffffffu, den, off);
    float invden = 1.f / fmaxf(den, 1e-16f);
    // pass 3: agg = sum alpha * z[src]
    float4 acc = make_float4(0.f, 0.f, 0.f, 0.f);
    for (int base = beg; base < end; base += 32) {
        int j = base + lane;
        float coeff = 0.f; int s = 0;
        if (j < end) {
            s = g_csrc[j];
            float x = g_ssrc[s] + sd;
            coeff = __expf(fmaxf(x, 0.01f * x) - mx) * invden;
        }
        int cnt = min(32, end - base);
        if (cnt == 32) {
            #pragma unroll 8
            for (int t = 0; t < 32; t++) {
                float c = __shfl_sync(0xffffffffu, coeff, t);
                int ss = __shfl_sync(0xffffffffu, s, t);
                float4 zv = *(const float4*)&g_z[ss * H + lane * 4];
                acc.x += c * zv.x; acc.y += c * zv.y;
                acc.z += c * zv.z; acc.w += c * zv.w;
            }
        } else {
            for (int t = 0; t < cnt; t++) {
                float c = __shfl_sync(0xffffffffu, coeff, t);
                int ss = __shfl_sync(0xffffffffu, s, t);
                float4 zv = *(const float4*)&g_z[ss * H + lane * 4];
                acc.x += c * zv.x; acc.y += c * zv.y;
                acc.z += c * zv.z; acc.w += c * zv.w;
            }
        }
    }
    float4 hs = *(const float4*)&g_hs[node * H + lane * 4];
    float4 o = make_float4(hi.x + hs.x + acc.x, hi.y + hs.y + acc.y,
                           hi.z + hs.z + acc.z, hi.w + hs.w + acc.w);
    *(float4*)&hout[node * H + lane * 4] = o;
}

// ---------------- output GEMM: out = h @ W_out^T + b_out ----------------
__global__ void k_out(const float* __restrict__ Wout, const float* __restrict__ bout,
                      const float* __restrict__ hfin, float* __restrict__ out) {
    __shared__ float ws[OUT_DIM * H];
    __shared__ float bs[OUT_DIM];
    for (int i = threadIdx.x; i < OUT_DIM * H; i += blockDim.x) ws[i] = Wout[i];
    if (threadIdx.x < OUT_DIM) bs[threadIdx.x] = bout[threadIdx.x];
    __syncthreads();
    int node = blockIdx.x * (blockDim.x >> 5) + (threadIdx.x >> 5);
    int lane = threadIdx.x & 31;
    if (node >= N_NODES) return;
    float4 hv = *(const float4*)&hfin[node * H + lane * 4];
    float vout = 0.f;
    #pragma unroll
    for (int o = 0; o < OUT_DIM; o++) {
        float4 wv = *(const float4*)&ws[o * H + lane * 4];
        float p = hv.x * wv.x + hv.y * wv.y + hv.z * wv.z + hv.w * wv.w;
        #pragma unroll
        for (int off = 16; off; off >>= 1) p += __shfl_xor_sync(0xffffffffu, p, off);
        if (lane == o) vout = p + bs[o];
    }
    if (lane < OUT_DIM) out[node * OUT_DIM + lane] = vout;
}

// ---------------- launch ----------------
extern "C" void kernel_launch(void* const* d_in, const int* in_sizes, int n_in,
                              void* d_out, int out_size) {
    const float* feats = (const float*)d_in[0];
    const float* maps  = (const float*)d_in[2];
    const int*   src   = (const int*)d_in[4];
    const int*   dst   = (const int*)d_in[5];
    const float* W_eh  = (const float*)d_in[6];
    const float* b_eh  = (const float*)d_in[7];
    const float* W_cat = (const float*)d_in[10];
    const float* b_cat = (const float*)d_in[11];
    const float* Ws1   = (const float*)d_in[12];
    const float* Wf1   = (const float*)d_in[13];
    const float* a1    = (const float*)d_in[14];
    const float* Ws2   = (const float*)d_in[15];
    const float* Wf2   = (const float*)d_in[16];
    const float* a2    = (const float*)d_in[17];
    const float* W_out = (const float*)d_in[18];
    const float* b_out = (const float*)d_in[19];
    float* out = (float*)d_out;

    float *hemb, *hA, *hB, *hs, *z;
    cudaGetSymbolAddress((void**)&hemb, g_hemb);
    cudaGetSymbolAddress((void**)&hA, g_hA);
    cudaGetSymbolAddress((void**)&hB, g_hB);
    cudaGetSymbolAddress((void**)&hs, g_hs);
    cudaGetSymbolAddress((void**)&z,  g_z);

    const int GB = (N_NODES + 63) / 64;       // 313 GEMM row blocks
    const int EB = (E_EDGES + 255) / 256;     // 2500
    const int WB = (N_NODES + 7) / 8;         // 2500 (8 warps/block)

    // CSR build (shared by both layers)
    k_zero_counters<<<(N_NODES + 255) / 256, 256>>>();
    k_hist<<<EB, 256>>>(dst);
    k_scan<<<1, 1024>>>();
    k_scatter<<<EB, 256>>>(src, dst);

    // input embedding + concat projection
    k_embed<<<N_NODES, H>>>(feats, W_eh, b_eh);
    k_gemm<MAPD + H, true, true, true><<<GB, 256>>>(maps, hemb, W_cat, b_cat, hA);

    // GAT layer 1: hA -> hB
    k_gemm<H, false, false, false><<<GB, 256>>>(hA, nullptr, Ws1, nullptr, hs);
    k_gemm<H, false, false, false><<<GB, 256>>>(hA, nullptr, Wf1, nullptr, z);
    k_sdot<<<WB, 256>>>(a1);
    k_gat<<<WB, 256>>>(hA, hB);

    // GAT layer 2: hB -> hA
    k_gemm<H, false, false, false><<<GB, 256>>>(hB, nullptr, Ws2, nullptr, hs);
    k_gemm<H, false, false, false><<<GB, 256>>>(hB, nullptr, Wf2, nullptr, z);
    k_sdot<<<WB, 256>>>(a2);
    k_gat<<<WB, 256>>>(hB, hA);

    // output projection
    k_out<<<WB, 256>>>(W_out, b_out, hA, out);
}

// round 2
// speedup vs baseline: 1.1390x; 1.1390x over previous
#include <cuda_runtime.h>
#include <cuda_bf16.h>

#define N_NODES 20000
#define E_EDGES 640000
#define IN_DIM  24
#define H       128
#define OUT_DIM 24
#define MAPD    512

typedef unsigned long long u64;

__device__ __forceinline__ u64 fma2(u64 a, u64 b, u64 c) {
    u64 d;
    asm("fma.rn.f32x2 %0, %1, %2, %3;" : "=l"(d) : "l"(a), "l"(b), "l"(c));
    return d;
}
__device__ __forceinline__ void unpack2(u64 v, float& lo, float& hi) {
    unsigned int l, h;
    asm("mov.b64 {%0,%1}, %2;" : "=r"(l), "=r"(h) : "l"(v));
    lo = __uint_as_float(l); hi = __uint_as_float(h);
}

// ---------------- scratch (device globals; no allocation) ----------------
__device__ float g_hemb[N_NODES * H];
__device__ float g_hA[N_NODES * H];
__device__ float g_hB[N_NODES * H];
__device__ float g_hs[N_NODES * H];
__device__ float g_z[N_NODES * H];
__device__ float g_ssrc[N_NODES];
__device__ float g_sdst[N_NODES];
__device__ int   g_offs[N_NODES + 1];
__device__ int   g_cnt[N_NODES];
__device__ int   g_cur[N_NODES];
__device__ int   g_csrc[E_EDGES];

// ---------------- CSR build ----------------
__global__ void k_zero() {
    int i = blockIdx.x * blockDim.x + threadIdx.x;
    if (i < N_NODES) { g_cnt[i] = 0; g_cur[i] = 0; }
}

// fused: blocks [0,2500) do histogram; blocks [2500, 12500) do embedding
__global__ void k_hist_embed(const int* __restrict__ dst,
                             const float* __restrict__ feats,
                             const float* __restrict__ W_eh,
                             const float* __restrict__ b_eh) {
    if (blockIdx.x < 2500) {
        int e = blockIdx.x * 256 + threadIdx.x;
        if (e < E_EDGES) atomicAdd(&g_cnt[dst[e]], 1);
        return;
    }
    int nb = blockIdx.x - 2500;
    __shared__ float f[2][IN_DIM];
    int half = threadIdx.x >> 7;
    int h = threadIdx.x & 127;
    int n = nb * 2 + half;
    if (h < IN_DIM) f[half][h] = feats[n * IN_DIM + h];
    __syncthreads();
    float acc = b_eh[h];
    #pragma unroll
    for (int k = 0; k < IN_DIM; k++) acc += f[half][k] * W_eh[h * IN_DIM + k];
    g_hemb[n * H + h] = acc;
}

// single-pass scan: 1024 threads x 20 elements each
__global__ void k_scan() {
    const int PER = 20;   // 1024*20 = 20480 >= 20000
    int t = threadIdx.x;
    int base = t * PER;
    int vals[PER];
    int s = 0;
    #pragma unroll
    for (int p = 0; p < PER; p++) {
        int i = base + p;
        int v = (i < N_NODES) ? g_cnt[i] : 0;
        vals[p] = s;   // exclusive-local
        s += v;
    }
    __shared__ int sh[1024];
    sh[t] = s;
    __syncthreads();
    #pragma unroll
    for (int off = 1; off < 1024; off <<= 1) {
        int x = (t >= off) ? sh[t - off] : 0;
        __syncthreads();
        sh[t] += x;
        __syncthreads();
    }
    int excl = sh[t] - s;
    #pragma unroll
    for (int p = 0; p < PER; p++) {
        int i = base + p;
        if (i < N_NODES) g_offs[i] = excl + vals[p];
    }
    if (t == 1023) g_offs[N_NODES] = sh[1023];
}

__global__ void k_scatter(const int* __restrict__ src, const int* __restrict__ dst) {
    int e = blockIdx.x * blockDim.x + threadIdx.x;
    if (e < E_EDGES) {
        int d = dst[e];
        int p = g_offs[d] + atomicAdd(&g_cur[d], 1);
        g_csrc[p] = src[e];
    }
}

// ---------------- tiled GEMM with packed f32x2 FMA ----------------
// C[N,128] = X[N,KDIM] @ W[128,KDIM]^T  (+bias)(relu)
// CONCAT: X[n,k] = (k<MAPD)? A0[n*MAPD+k] : A1[n*H + k-MAPD]
// SDOT:   gridDim.y==2, y picks (W0->C0) or (W1->C1); y==1 also computes
//         g_ssrc/g_sdst = C1 @ avec halves in the epilogue.
template <int KDIM, bool DO_RELU, bool HAS_BIAS, bool CONCAT, bool SDOT>
__global__ void __launch_bounds__(256)
k_gemm(const float* __restrict__ A0, const float* __restrict__ A1,
       const float* __restrict__ W0, const float* __restrict__ W1,
       const float* __restrict__ bias, const float* __restrict__ avec,
       float* __restrict__ C0, float* __restrict__ C1) {
    const int BM = 64, BK = 16;
    __shared__ float As2[BK][2 * BM + 4];   // duplicated A values
    __shared__ float Bs[BK][H + 4];

    const float* W = SDOT ? (blockIdx.y ? W1 : W0) : W0;
    float* C       = SDOT ? (blockIdx.y ? C1 : C0) : C0;

    int tid = threadIdx.x;
    int row0 = blockIdx.x * BM;
    int tx = tid & 31;   // col pair group: cols tx*4..+3
    int ty = tid >> 5;   // rows ty*8..+7

    u64 acc[8][2];
    #pragma unroll
    for (int i = 0; i < 8; i++) { acc[i][0] = 0ull; acc[i][1] = 0ull; }

    int kinA = tid & 15, rrA = tid >> 4;

    for (int k0 = 0; k0 < KDIM; k0 += BK) {
        #pragma unroll
        for (int p = 0; p < 4; p++) {
            int r = rrA + p * 16;
            int grow = row0 + r;
            int gk = k0 + kinA;
            float v = 0.f;
            if (grow < N_NODES) {
                if (CONCAT) v = (gk < MAPD) ? A0[grow * MAPD + gk]
                                            : A1[grow * H + (gk - MAPD)];
                else        v = A0[grow * KDIM + gk];
            }
            *(float2*)&As2[kinA][2 * r] = make_float2(v, v);
        }
        #pragma unroll
        for (int p = 0; p < 8; p++) {
            int h = (tid >> 4) + p * 16;
            int gk = k0 + (tid & 15);
            Bs[tid & 15][h] = W[h * KDIM + gk];
        }
        __syncthreads();
        #pragma unroll
        for (int kk = 0; kk < BK; kk++) {
            ulonglong2 a01 = *(const ulonglong2*)&As2[kk][ty * 16];
            ulonglong2 a23 = *(const ulonglong2*)&As2[kk][ty * 16 + 4];
            ulonglong2 a45 = *(const ulonglong2*)&As2[kk][ty * 16 + 8];
            ulonglong2 a67 = *(const ulonglong2*)&As2[kk][ty * 16 + 12];
            ulonglong2 bq  = *(const ulonglong2*)&Bs[kk][tx * 4];
            u64 av[8] = {a01.x, a01.y, a23.x, a23.y, a45.x, a45.y, a67.x, a67.y};
            #pragma unroll
            for (int i = 0; i < 8; i++) {
                acc[i][0] = fma2(av[i], bq.x, acc[i][0]);
                acc[i][1] = fma2(av[i], bq.y, acc[i][1]);
            }
        }
        __syncthreads();
    }

    float cc[8][4];
    #pragma unroll
    for (int i = 0; i < 8; i++) {
        unpack2(acc[i][0], cc[i][0], cc[i][1]);
        unpack2(acc[i][1], cc[i][2], cc[i][3]);
    }

    float4 bv = make_float4(0.f, 0.f, 0.f, 0.f);
    if (HAS_BIAS) bv = *(const float4*)&bias[tx * 4];
    #pragma unroll
    for (int i = 0; i < 8; i++) {
        int row = row0 + ty * 8 + i;
        if (row < N_NODES) {
            float4 r;
            r.x = cc[i][0] + bv.x; r.y = cc[i][1] + bv.y;
            r.z = cc[i][2] + bv.z; r.w = cc[i][3] + bv.w;
            if (DO_RELU) {
                r.x = fmaxf(r.x, 0.f); r.y = fmaxf(r.y, 0.f);
                r.z = fmaxf(r.z, 0.f); r.w = fmaxf(r.w, 0.f);
            }
            *(float4*)&C[row * H + tx * 4] = r;
        }
    }

    if (SDOT) {
        if (blockIdx.y == 1) {
            float4 av0 = *(const float4*)&avec[tx * 4];
            float4 av1 = *(const float4*)&avec[H + tx * 4];
            #pragma unroll
            for (int i = 0; i < 8; i++) {
                int row = row0 + ty * 8 + i;
                if (row >= N_NODES) break;
                float p0 = cc[i][0] * av0.x + cc[i][1] * av0.y +
                           cc[i][2] * av0.z + cc[i][3] * av0.w;
                float p1 = cc[i][0] * av1.x + cc[i][1] * av1.y +
                           cc[i][2] * av1.z + cc[i][3] * av1.w;
                #pragma unroll
                for (int off = 16; off; off >>= 1) {
                    p0 += __shfl_xor_sync(0xffffffffu, p0, off);
                    p1 += __shfl_xor_sync(0xffffffffu, p1, off);
                }
                if (tx == 0) { g_ssrc[row] = p0; g_sdst[row] = p1; }
            }
        }
    }
}

// ---------------- fused GAT edge kernel: warp per dst node ----------------
__global__ void k_gat(const float* __restrict__ hin, float* __restrict__ hout) {
    int node = blockIdx.x * (blockDim.x >> 5) + (threadIdx.x >> 5);
    int lane = threadIdx.x & 31;
    if (node >= N_NODES) return;
    int beg = g_offs[node], end = g_offs[node + 1];
    float4 hi = *(const float4*)&hin[node * H + lane * 4];
    if (beg == end) {
        float4 o = make_float4(2.f * hi.x, 2.f * hi.y, 2.f * hi.z, 2.f * hi.w);
        *(float4*)&hout[node * H + lane * 4] = o;
        return;
    }
    float sd = g_sdst[node];
    float mx = -3.0e38f;
    for (int j = beg + lane; j < end; j += 32) {
        float x = g_ssrc[g_csrc[j]] + sd;
        mx = fmaxf(mx, fmaxf(x, 0.01f * x));
    }
    #pragma unroll
    for (int off = 16; off; off >>= 1) mx = fmaxf(mx, __shfl_xor_sync(0xffffffffu, mx, off));
    float den = 0.f;
    for (int j = beg + lane; j < end; j += 32) {
        float x = g_ssrc[g_csrc[j]] + sd;
        den += __expf(fmaxf(x, 0.01f * x) - mx);
    }
    #pragma unroll
    for (int off = 16; off; off >>= 1) den += __shfl_xor_sync(0xffffffffu, den, off);
    float invden = 1.f / fmaxf(den, 1e-16f);
    float4 acc = make_float4(0.f, 0.f, 0.f, 0.f);
    for (int base = beg; base < end; base += 32) {
        int j = base + lane;
        float coeff = 0.f; int s = 0;
        if (j < end) {
            s = g_csrc[j];
            float x = g_ssrc[s] + sd;
            coeff = __expf(fmaxf(x, 0.01f * x) - mx) * invden;
        }
        int cnt = min(32, end - base);
        if (cnt == 32) {
            #pragma unroll 8
            for (int t = 0; t < 32; t++) {
                float c = __shfl_sync(0xffffffffu, coeff, t);
                int ss = __shfl_sync(0xffffffffu, s, t);
                float4 zv = *(const float4*)&g_z[ss * H + lane * 4];
                acc.x += c * zv.x; acc.y += c * zv.y;
                acc.z += c * zv.z; acc.w += c * zv.w;
            }
        } else {
            for (int t = 0; t < cnt; t++) {
                float c = __shfl_sync(0xffffffffu, coeff, t);
                int ss = __shfl_sync(0xffffffffu, s, t);
                float4 zv = *(const float4*)&g_z[ss * H + lane * 4];
                acc.x += c * zv.x; acc.y += c * zv.y;
                acc.z += c * zv.z; acc.w += c * zv.w;
            }
        }
    }
    float4 hs = *(const float4*)&g_hs[node * H + lane * 4];
    float4 o = make_float4(hi.x + hs.x + acc.x, hi.y + hs.y + acc.y,
                           hi.z + hs.z + acc.z, hi.w + hs.w + acc.w);
    *(float4*)&hout[node * H + lane * 4] = o;
}

// ---------------- output GEMM: out = h @ W_out^T + b_out ----------------
__global__ void k_out(const float* __restrict__ Wout, const float* __restrict__ bout,
                      const float* __restrict__ hfin, float* __restrict__ out) {
    __shared__ float ws[OUT_DIM * H];
    __shared__ float bs[OUT_DIM];
    for (int i = threadIdx.x; i < OUT_DIM * H; i += blockDim.x) ws[i] = Wout[i];
    if (threadIdx.x < OUT_DIM) bs[threadIdx.x] = bout[threadIdx.x];
    __syncthreads();
    int node = blockIdx.x * (blockDim.x >> 5) + (threadIdx.x >> 5);
    int lane = threadIdx.x & 31;
    if (node >= N_NODES) return;
    float4 hv = *(const float4*)&hfin[node * H + lane * 4];
    float vout = 0.f;
    #pragma unroll
    for (int o = 0; o < OUT_DIM; o++) {
        float4 wv = *(const float4*)&ws[o * H + lane * 4];
        float p = hv.x * wv.x + hv.y * wv.y + hv.z * wv.z + hv.w * wv.w;
        #pragma unroll
        for (int off = 16; off; off >>= 1) p += __shfl_xor_sync(0xffffffffu, p, off);
        if (lane == o) vout = p + bs[o];
    }
    if (lane < OUT_DIM) out[node * OUT_DIM + lane] = vout;
}

// ---------------- launch ----------------
extern "C" void kernel_launch(void* const* d_in, const int* in_sizes, int n_in,
                              void* d_out, int out_size) {
    const float* feats = (const float*)d_in[0];
    const float* maps  = (const float*)d_in[2];
    const int*   src   = (const int*)d_in[4];
    const int*   dst   = (const int*)d_in[5];
    const float* W_eh  = (const float*)d_in[6];
    const float* b_eh  = (const float*)d_in[7];
    const float* W_cat = (const float*)d_in[10];
    const float* b_cat = (const float*)d_in[11];
    const float* Ws1   = (const float*)d_in[12];
    const float* Wf1   = (const float*)d_in[13];
    const float* a1    = (const float*)d_in[14];
    const float* Ws2   = (const float*)d_in[15];
    const float* Wf2   = (const float*)d_in[16];
    const float* a2    = (const float*)d_in[17];
    const float* W_out = (const float*)d_in[18];
    const float* b_out = (const float*)d_in[19];
    float* out = (float*)d_out;

    float *hemb, *hA, *hB, *hs, *z;
    cudaGetSymbolAddress((void**)&hemb, g_hemb);
    cudaGetSymbolAddress((void**)&hA, g_hA);
    cudaGetSymbolAddress((void**)&hB, g_hB);
    cudaGetSymbolAddress((void**)&hs, g_hs);
    cudaGetSymbolAddress((void**)&z,  g_z);

    const int GB = (N_NODES + 63) / 64;   // 313
    const int EB = (E_EDGES + 255) / 256; // 2500
    const int WB = (N_NODES + 7) / 8;     // 2500

    k_zero<<<(N_NODES + 255) / 256, 256>>>();
    k_hist_embed<<<EB + 10000, 256>>>(dst, feats, W_eh, b_eh);
    k_scan<<<1, 1024>>>();
    k_scatter<<<EB, 256>>>(src, dst);

    // concat projection (relu)
    k_gemm<MAPD + H, true, true, true, false><<<GB, 256>>>(
        maps, hemb, W_cat, nullptr, b_cat, nullptr, hA, nullptr);

    // GAT layer 1: hA -> hB  (fused Ws/Wf GEMM + sdot epilogue)
    k_gemm<H, false, false, false, true><<<dim3(GB, 2), 256>>>(
        hA, nullptr, Ws1, Wf1, nullptr, a1, hs, z);
    k_gat<<<WB, 256>>>(hA, hB);

    // GAT layer 2: hB -> hA
    k_gemm<H, false, false, false, true><<<dim3(GB, 2), 256>>>(
        hB, nullptr, Ws2, Wf2, nullptr, a2, hs, z);
    k_gat<<<WB, 256>>>(hB, hA);

    k_out<<<WB, 256>>>(W_out, b_out, hA, out);
}